// round 12
// baseline (speedup 1.0000x reference)
#include <cuda_runtime.h>
#include <cuda_fp16.h>
#include <math.h>

#define N_NODES 100000
#define N_EDGES 800000
#define VOCAB   256
#define DIM     256
#define N_MASK  10000
#define R2      16
#define SCAN_B  1024
#define NBLK    ((N_NODES + SCAN_B - 1) / SCAN_B)   // 98
#define EB      ((N_EDGES + 255) / 256)             // 3125 edge blocks in hist
#define MB      ((N_MASK + 255) / 256)              // 40 mask blocks in hist
#define SAGG_STRIDE 10

// ---------------- zeroed-per-run region (single memset) ----------------
struct ZeroRegion {
    int deg[N_NODES];
    unsigned long long tilestate[NBLK];   // (flag<<32)|sum : 0=empty,1=agg,2=prefix
    unsigned char need[N_NODES];
    unsigned char flag[N_NODES];          // masked-node indicator
};
__device__ ZeroRegion g_z;

// ---------------- other scratch ----------------
__device__ float g_dinv[N_NODES];
__device__ int   g_rowstart[N_NODES + 1];
__device__ int   g_cursor[N_NODES];
__device__ int2  g_csr[N_EDGES];          // .x = src | (x[src]<<20), .y = norm weight bits
__device__ uint4 g_EW1h[VOCAB * 32];              // fp16 EW1: 128 KB
__device__ uint4 g_h1h[(size_t)N_NODES * 32];     // fp16 h1 rows (512 B each)

// ---------------- helpers ----------------
__device__ __forceinline__ unsigned long long pk2(float x, float y) {
    unsigned long long r;
    asm("mov.b64 %0, {%1,%2};" : "=l"(r) : "f"(x), "f"(y));
    return r;
}
__device__ __forceinline__ float2 upk2(unsigned long long v) {
    float2 f;
    asm("mov.b64 {%0,%1}, %2;" : "=f"(f.x), "=f"(f.y) : "l"(v));
    return f;
}
__device__ __forceinline__ void fma2p(unsigned long long& d,
                                      unsigned long long a,
                                      unsigned long long b) {
    asm("fma.rn.f32x2 %0, %1, %2, %0;" : "+l"(d) : "l"(a), "l"(b));
}
__device__ __forceinline__ int warp_incl_scan(int v, int lane) {
#pragma unroll
    for (int off = 1; off < 32; off <<= 1) {
        int n = __shfl_up_sync(0xFFFFFFFFu, v, off);
        if (lane >= off) v += n;
    }
    return v;
}

// ---------------- hist over edges + mask flags in spare blocks -------------
__global__ void k_hist_flag(const int* __restrict__ dst, const int* __restrict__ mask) {
    const int b = blockIdx.x;
    if (b < EB) {
        int i = b * 256 + threadIdx.x;
        if (i < N_EDGES) atomicAdd(&g_z.deg[dst[i]], 1);
    } else {
        int i = (b - EB) * 256 + threadIdx.x;
        if (i < N_MASK) {
            int m = mask[i];
            g_z.flag[m] = 1;
            g_z.need[m] = 1;
        }
    }
}

// ---------------- single-pass decoupled-lookback scan ----------------------
// exclusive scan of deg -> rowstart/cursor; also dinv. 98 tiles, all resident.
__global__ void __launch_bounds__(SCAN_B) k_scan_lb() {
    __shared__ int wsum[32];
    __shared__ int s_prefix;
    const int t    = threadIdx.x;
    const int lane = t & 31;
    const int wid  = t >> 5;
    const int bid  = blockIdx.x;
    const int i    = bid * SCAN_B + t;
    const int cnt  = (i < N_NODES) ? g_z.deg[i] : 0;

    int incl = warp_incl_scan(cnt, lane);
    if (lane == 31) wsum[wid] = incl;
    __syncthreads();
    if (wid == 0) wsum[lane] = warp_incl_scan(wsum[lane], lane);
    __syncthreads();
    const int block_excl = incl - cnt + (wid ? wsum[wid - 1] : 0);
    const int agg = wsum[31];

    volatile unsigned long long* ts = (volatile unsigned long long*)g_z.tilestate;
    if (t == 0) {
        if (bid == 0) {
            ts[0] = (2ULL << 32) | (unsigned)agg;   // inclusive prefix
            s_prefix = 0;
        } else {
            ts[bid] = (1ULL << 32) | (unsigned)agg; // aggregate only
        }
    }
    __threadfence();
    if (bid > 0 && t == 0) {
        int run = 0;
        int idx = bid - 1;
        while (idx >= 0) {
            unsigned long long s;
            do { s = ts[idx]; } while ((s >> 32) == 0ULL);
            run += (int)(unsigned)s;
            if ((s >> 32) == 2ULL) break;
            idx--;
        }
        ts[bid] = (2ULL << 32) | (unsigned)(run + agg);
        s_prefix = run;
    }
    __syncthreads();

    const int excl = s_prefix + block_excl;
    if (i < N_NODES) {
        g_rowstart[i] = excl;
        g_cursor[i]   = excl;
        g_dinv[i]     = rsqrtf((float)(cnt + 1));
        if (i == N_NODES - 1) g_rowstart[N_NODES] = excl + cnt;
    }
}

// ---------------- fill CSR + propagate need from masked dst ----------------
__global__ void k_fill(const int* __restrict__ src, const int* __restrict__ dst,
                       const int* __restrict__ x) {
    int i = blockIdx.x * blockDim.x + threadIdx.x;
    if (i < N_EDGES) {
        int s = src[i];
        int d = dst[i];
        float w = g_dinv[s] * g_dinv[d];
        int p = atomicAdd(&g_cursor[d], 1);
        g_csr[p] = make_int2(s | (x[s] << 20), __float_as_int(w));
        if (g_z.flag[d]) g_z.need[s] = 1;
    }
}

// ---------------- EW1 = emb @ W1 -> fp16 ----------------
__global__ void k_ew1(const float* __restrict__ emb, const float* __restrict__ W1) {
    __shared__ float se[DIM];
    const int v = blockIdx.x;
    const int c = threadIdx.x;
    se[c] = emb[v * DIM + c];
    __syncthreads();
    float acc = 0.f;
#pragma unroll 8
    for (int k = 0; k < DIM; k++) acc = fmaf(se[k], W1[k * DIM + c], acc);
    reinterpret_cast<__half*>(g_EW1h)[v * DIM + c] = __float2half(acc);
}

// ---------------- layer 1: h1 = relu(aggregate(EW1[x]) + b1), warp/node ----
__global__ void k_layer1(const int* __restrict__ x, const float* __restrict__ b1) {
    const int warp = blockIdx.x * (blockDim.x >> 5) + (threadIdx.x >> 5);
    if (warp >= N_NODES) return;
    const int n = warp;
    if (!g_z.need[n]) return;
    const int lane = threadIdx.x & 31;

    const float dn = g_dinv[n];
    float2 a0 = make_float2(0.f, 0.f), a1 = a0, a2 = a0, a3 = a0;

    // self loop
    {
        int   v = x[n];
        float w = dn * dn;
        uint4 r = g_EW1h[v * 32 + lane];
        float2 f0 = __half22float2(*reinterpret_cast<__half2*>(&r.x));
        float2 f1 = __half22float2(*reinterpret_cast<__half2*>(&r.y));
        float2 f2 = __half22float2(*reinterpret_cast<__half2*>(&r.z));
        float2 f3 = __half22float2(*reinterpret_cast<__half2*>(&r.w));
        a0.x = fmaf(w, f0.x, a0.x); a0.y = fmaf(w, f0.y, a0.y);
        a1.x = fmaf(w, f1.x, a1.x); a1.y = fmaf(w, f1.y, a1.y);
        a2.x = fmaf(w, f2.x, a2.x); a2.y = fmaf(w, f2.y, a2.y);
        a3.x = fmaf(w, f3.x, a3.x); a3.y = fmaf(w, f3.y, a3.y);
    }

    const int e0 = g_rowstart[n];
    const int e1 = g_rowstart[n + 1];
    for (int e = e0; e < e1; e++) {
        int2 pw = g_csr[e];
        int   v = pw.x >> 20;
        float w = __int_as_float(pw.y);
        uint4 r = g_EW1h[v * 32 + lane];
        float2 f0 = __half22float2(*reinterpret_cast<__half2*>(&r.x));
        float2 f1 = __half22float2(*reinterpret_cast<__half2*>(&r.y));
        float2 f2 = __half22float2(*reinterpret_cast<__half2*>(&r.z));
        float2 f3 = __half22float2(*reinterpret_cast<__half2*>(&r.w));
        a0.x = fmaf(w, f0.x, a0.x); a0.y = fmaf(w, f0.y, a0.y);
        a1.x = fmaf(w, f1.x, a1.x); a1.y = fmaf(w, f1.y, a1.y);
        a2.x = fmaf(w, f2.x, a2.x); a2.y = fmaf(w, f2.y, a2.y);
        a3.x = fmaf(w, f3.x, a3.x); a3.y = fmaf(w, f3.y, a3.y);
    }

    const float2* B2 = reinterpret_cast<const float2*>(b1);
    float2 bb0 = B2[lane * 4 + 0], bb1 = B2[lane * 4 + 1];
    float2 bb2 = B2[lane * 4 + 2], bb3 = B2[lane * 4 + 3];
    a0.x = fmaxf(a0.x + bb0.x, 0.f); a0.y = fmaxf(a0.y + bb0.y, 0.f);
    a1.x = fmaxf(a1.x + bb1.x, 0.f); a1.y = fmaxf(a1.y + bb1.y, 0.f);
    a2.x = fmaxf(a2.x + bb2.x, 0.f); a2.y = fmaxf(a2.y + bb2.y, 0.f);
    a3.x = fmaxf(a3.x + bb3.x, 0.f); a3.y = fmaxf(a3.y + bb3.y, 0.f);

    uint4 o;
    *reinterpret_cast<__half2*>(&o.x) = __float22half2_rn(a0);
    *reinterpret_cast<__half2*>(&o.y) = __float22half2_rn(a1);
    *reinterpret_cast<__half2*>(&o.z) = __float22half2_rn(a2);
    *reinterpret_cast<__half2*>(&o.w) = __float22half2_rn(a3);
    g_h1h[(size_t)n * 32 + lane] = o;
}

// ---------------- layer 2: agg(fp16 h1) -> f32x2 GEMM -> log_softmax ------
__global__ void __launch_bounds__(256) k_layer2(const int* __restrict__ mask,
                                                const float* __restrict__ W2,
                                                const float* __restrict__ b2,
                                                float* __restrict__ out) {
    __shared__ unsigned long long sagg2[DIM * SAGG_STRIDE];  // 20 KB
    const int t  = threadIdx.x;
    const int r0 = blockIdx.x * R2;
    const __half* H = reinterpret_cast<const __half*>(g_h1h);

    // ---- stage A: aggregate h1 rows; thread t owns feature dim t ----
    float a[R2];
    for (int i = 0; i < R2; i++) {
        const int m  = mask[r0 + i];
        const float dm = g_dinv[m];
        float acc = dm * dm * __half2float(H[(size_t)m * DIM + t]);
        const int e0 = g_rowstart[m];
        const int e1 = g_rowstart[m + 1];
        for (int e = e0; e < e1; e++) {
            int2 pw = g_csr[e];
            int   s = pw.x & 0xFFFFF;
            float w = __int_as_float(pw.y);
            acc = fmaf(w, __half2float(H[(size_t)s * DIM + t]), acc);
        }
        a[i] = acc;
    }
#pragma unroll
    for (int j = 0; j < 8; j++)
        sagg2[t * SAGG_STRIDE + j] = pk2(a[2 * j], a[2 * j + 1]);
    __syncthreads();

    // ---- stage B: packed f32x2 GEMM ----
    unsigned long long o2[8];
    {
        const float bb = b2[t];
        unsigned long long bbp = pk2(bb, bb);
#pragma unroll
        for (int j = 0; j < 8; j++) o2[j] = bbp;
    }
#pragma unroll 4
    for (int k = 0; k < DIM; k++) {
        const float w = W2[k * DIM + t];
        const unsigned long long ww = pk2(w, w);
        const ulonglong2* A2 = reinterpret_cast<const ulonglong2*>(sagg2 + k * SAGG_STRIDE);
        ulonglong2 p0 = A2[0], p1 = A2[1], p2 = A2[2], p3 = A2[3];
        fma2p(o2[0], p0.x, ww); fma2p(o2[1], p0.y, ww);
        fma2p(o2[2], p1.x, ww); fma2p(o2[3], p1.y, ww);
        fma2p(o2[4], p2.x, ww); fma2p(o2[5], p2.y, ww);
        fma2p(o2[6], p3.x, ww); fma2p(o2[7], p3.y, ww);
    }
    __syncthreads();

    float* sout = reinterpret_cast<float*>(sagg2);   // 16 KB <= 20 KB
#pragma unroll
    for (int j = 0; j < 8; j++) {
        float2 f = upk2(o2[j]);
        sout[(2 * j) * DIM + t]     = f.x;
        sout[(2 * j + 1) * DIM + t] = f.y;
    }
    __syncthreads();

    // ---- stage C: per-row log_softmax ----
    const int wi   = t >> 5;
    const int lane = t & 31;
#pragma unroll
    for (int rr = 0; rr < 2; rr++) {
        const int i = wi + rr * 8;
        float v[8];
        float mx = -INFINITY;
#pragma unroll
        for (int j = 0; j < 8; j++) {
            v[j] = sout[i * DIM + lane + j * 32];
            mx = fmaxf(mx, v[j]);
        }
#pragma unroll
        for (int off = 16; off > 0; off >>= 1)
            mx = fmaxf(mx, __shfl_xor_sync(0xFFFFFFFFu, mx, off));
        float s = 0.f;
#pragma unroll
        for (int j = 0; j < 8; j++) s += expf(v[j] - mx);
#pragma unroll
        for (int off = 16; off > 0; off >>= 1)
            s += __shfl_xor_sync(0xFFFFFFFFu, s, off);
        const float lse = mx + logf(s);
        float* orow = out + (size_t)(r0 + i) * DIM;
#pragma unroll
        for (int j = 0; j < 8; j++) orow[lane + j * 32] = v[j] - lse;
    }
}

// ---------------- launch ----------------
extern "C" void kernel_launch(void* const* d_in, const int* in_sizes, int n_in,
                              void* d_out, int out_size) {
    const int*   x    = (const int*)d_in[0];
    const int*   esrc = (const int*)d_in[1];
    const int*   edst = ((const int*)d_in[1]) + N_EDGES;
    const int*   mask = (const int*)d_in[2];
    const float* emb  = (const float*)d_in[3];
    const float* W1   = (const float*)d_in[4];
    const float* b1   = (const float*)d_in[5];
    const float* W2   = (const float*)d_in[6];
    const float* b2   = (const float*)d_in[7];
    float*       out  = (float*)d_out;

    void* p_z = nullptr;
    cudaGetSymbolAddress(&p_z, g_z);
    cudaMemsetAsync(p_z, 0, sizeof(ZeroRegion), 0);                    // launch 1

    const int TB = 256;
    k_hist_flag<<<EB + MB, TB>>>(edst, mask);                          // launch 2
    k_scan_lb<<<NBLK, SCAN_B>>>();                                     // launch 3
    k_fill<<<(N_EDGES + TB - 1) / TB, TB>>>(esrc, edst, x);            // launch 4
    k_ew1<<<VOCAB, DIM>>>(emb, W1);                                    // launch 5
    k_layer1<<<(N_NODES + 7) / 8, 256>>>(x, b1);                       // launch 6 (profiled)
    k_layer2<<<N_MASK / R2, 256>>>(mask, W2, b2, out);                 // launch 7
}

// round 13
// speedup vs baseline: 1.5461x; 1.5461x over previous
#include <cuda_runtime.h>
#include <cuda_fp16.h>
#include <math.h>

#define N_NODES 100000
#define N_EDGES 800000
#define VOCAB   256
#define DIM     256
#define N_MASK  10000
#define R2      16
#define SCAN_B  1024
#define NBLK    ((N_NODES + SCAN_B - 1) / SCAN_B)   // 98
#define SAGG_STRIDE 10   // ull stride per k-row (80B: 16B-aligned, 4-way max conflict)

// ---------------- zeroed-per-run region (single memset) ----------------
struct ZeroRegion {
    int deg[N_NODES];
    unsigned char need[N_NODES];
};
__device__ ZeroRegion g_z;

// ---------------- other scratch ----------------
__device__ float g_dinv[N_NODES];
__device__ int   g_rowstart[N_NODES + 1];
__device__ int   g_cursor[N_NODES];
__device__ int2  g_csr[N_EDGES];          // .x = src | (x[src]<<20), .y = norm weight bits
__device__ int   g_blocksum[NBLK];
__device__ int   g_blockoff[NBLK];
__device__ uint4 g_EW1h[VOCAB * 32];              // fp16 EW1: 128 KB
__device__ uint4 g_h1h[(size_t)N_NODES * 32];     // fp16 h1 rows (512 B each)

// ---------------- helpers ----------------
__device__ __forceinline__ unsigned long long pk2(float x, float y) {
    unsigned long long r;
    asm("mov.b64 %0, {%1,%2};" : "=l"(r) : "f"(x), "f"(y));
    return r;
}
__device__ __forceinline__ float2 upk2(unsigned long long v) {
    float2 f;
    asm("mov.b64 {%0,%1}, %2;" : "=f"(f.x), "=f"(f.y) : "l"(v));
    return f;
}
__device__ __forceinline__ void fma2p(unsigned long long& d,
                                      unsigned long long a,
                                      unsigned long long b) {
    asm("fma.rn.f32x2 %0, %1, %2, %0;" : "+l"(d) : "l"(a), "l"(b));
}
__device__ __forceinline__ int warp_incl_scan(int v, int lane) {
#pragma unroll
    for (int off = 1; off < 32; off <<= 1) {
        int n = __shfl_up_sync(0xFFFFFFFFu, v, off);
        if (lane >= off) v += n;
    }
    return v;
}

// ---------------- CSR construction ----------------
__global__ void k_hist(const int* __restrict__ dst) {
    int i = blockIdx.x * blockDim.x + threadIdx.x;
    if (i < N_EDGES) atomicAdd(&g_z.deg[dst[i]], 1);
}

__global__ void __launch_bounds__(SCAN_B) k_blocksum() {
    __shared__ int wsum[32];
    const int t    = threadIdx.x;
    const int lane = t & 31;
    const int wid  = t >> 5;
    const int i    = blockIdx.x * SCAN_B + t;
    int v = (i < N_NODES) ? g_z.deg[i] : 0;
#pragma unroll
    for (int off = 16; off > 0; off >>= 1) v += __shfl_xor_sync(0xFFFFFFFFu, v, off);
    if (lane == 0) wsum[wid] = v;
    __syncthreads();
    if (wid == 0) {
        int s = wsum[lane];
#pragma unroll
        for (int off = 16; off > 0; off >>= 1) s += __shfl_xor_sync(0xFFFFFFFFu, s, off);
        if (lane == 0) g_blocksum[blockIdx.x] = s;
    }
}

__global__ void k_scanblocks() {
    __shared__ int ws[4];
    const int t    = threadIdx.x;     // 128 threads
    const int lane = t & 31;
    const int wid  = t >> 5;
    int v = (t < NBLK) ? g_blocksum[t] : 0;
    int incl = warp_incl_scan(v, lane);
    if (lane == 31) ws[wid] = incl;
    __syncthreads();
    if (t == 0) {
        int run = 0;
#pragma unroll
        for (int w = 0; w < 4; w++) { int tmp = ws[w]; ws[w] = run; run += tmp; }
    }
    __syncthreads();
    if (t < NBLK) g_blockoff[t] = incl - v + ws[wid];
}

__global__ void __launch_bounds__(SCAN_B) k_scanfinal() {
    __shared__ int wsum[32];
    const int t    = threadIdx.x;
    const int lane = t & 31;
    const int wid  = t >> 5;
    const int i    = blockIdx.x * SCAN_B + t;
    const int cnt  = (i < N_NODES) ? g_z.deg[i] : 0;
    int incl = warp_incl_scan(cnt, lane);
    if (lane == 31) wsum[wid] = incl;
    __syncthreads();
    if (wid == 0) wsum[lane] = warp_incl_scan(wsum[lane], lane);
    __syncthreads();
    int excl = incl - cnt + (wid ? wsum[wid - 1] : 0) + g_blockoff[blockIdx.x];
    if (i < N_NODES) {
        g_rowstart[i] = excl;
        g_cursor[i]   = excl;
        g_dinv[i]     = rsqrtf((float)(cnt + 1));
        if (i == N_NODES - 1) g_rowstart[N_NODES] = excl + cnt;
    }
}

// fill CSR with packed (src | x[src]<<20) + precomputed norm weight
__global__ void k_fill(const int* __restrict__ src, const int* __restrict__ dst,
                       const int* __restrict__ x) {
    int i = blockIdx.x * blockDim.x + threadIdx.x;
    if (i < N_EDGES) {
        int s = src[i];
        int d = dst[i];
        float w = g_dinv[s] * g_dinv[d];
        int p = atomicAdd(&g_cursor[d], 1);
        g_csr[p] = make_int2(s | (x[s] << 20), __float_as_int(w));
    }
}

// mark nodes whose h1 is consumed by layer 2
__global__ void k_mark(const int* __restrict__ mask) {
    const int w = blockIdx.x * (blockDim.x >> 5) + (threadIdx.x >> 5);
    if (w >= N_MASK) return;
    const int lane = threadIdx.x & 31;
    const int m = mask[w];
    if (lane == 0) g_z.need[m] = 1;
    const int e0 = g_rowstart[m];
    const int e1 = g_rowstart[m + 1];
    for (int e = e0 + lane; e < e1; e += 32) g_z.need[g_csr[e].x & 0xFFFFF] = 1;
}

// ---------------- EW1 = emb @ W1 -> fp16; 4 independent acc chains ---------
__global__ void k_ew1(const float* __restrict__ emb, const float* __restrict__ W1) {
    __shared__ float se[DIM];
    const int v = blockIdx.x;
    const int c = threadIdx.x;
    se[c] = emb[v * DIM + c];
    __syncthreads();
    float a0 = 0.f, a1 = 0.f, a2 = 0.f, a3 = 0.f;
#pragma unroll 4
    for (int k = 0; k < DIM; k += 4) {
        a0 = fmaf(se[k    ], W1[(k    ) * DIM + c], a0);
        a1 = fmaf(se[k + 1], W1[(k + 1) * DIM + c], a1);
        a2 = fmaf(se[k + 2], W1[(k + 2) * DIM + c], a2);
        a3 = fmaf(se[k + 3], W1[(k + 3) * DIM + c], a3);
    }
    reinterpret_cast<__half*>(g_EW1h)[v * DIM + c] =
        __float2half((a0 + a1) + (a2 + a3));
}

// ---------------- layer 1: h1 = relu(aggregate(EW1[x]) + b1), warp/node ----
__global__ void k_layer1(const int* __restrict__ x, const float* __restrict__ b1) {
    const int warp = blockIdx.x * (blockDim.x >> 5) + (threadIdx.x >> 5);
    if (warp >= N_NODES) return;
    const int n = warp;
    if (!g_z.need[n]) return;
    const int lane = threadIdx.x & 31;

    const float dn = g_dinv[n];
    float2 a0 = make_float2(0.f, 0.f), a1 = a0, a2 = a0, a3 = a0;

    // self loop
    {
        int   v = x[n];
        float w = dn * dn;
        uint4 r = g_EW1h[v * 32 + lane];
        float2 f0 = __half22float2(*reinterpret_cast<__half2*>(&r.x));
        float2 f1 = __half22float2(*reinterpret_cast<__half2*>(&r.y));
        float2 f2 = __half22float2(*reinterpret_cast<__half2*>(&r.z));
        float2 f3 = __half22float2(*reinterpret_cast<__half2*>(&r.w));
        a0.x = fmaf(w, f0.x, a0.x); a0.y = fmaf(w, f0.y, a0.y);
        a1.x = fmaf(w, f1.x, a1.x); a1.y = fmaf(w, f1.y, a1.y);
        a2.x = fmaf(w, f2.x, a2.x); a2.y = fmaf(w, f2.y, a2.y);
        a3.x = fmaf(w, f3.x, a3.x); a3.y = fmaf(w, f3.y, a3.y);
    }

    const int e0 = g_rowstart[n];
    const int e1 = g_rowstart[n + 1];
    for (int e = e0; e < e1; e++) {
        int2 pw = g_csr[e];               // lane-uniform 8B broadcast
        int   v = pw.x >> 20;
        float w = __int_as_float(pw.y);
        uint4 r = g_EW1h[v * 32 + lane];
        float2 f0 = __half22float2(*reinterpret_cast<__half2*>(&r.x));
        float2 f1 = __half22float2(*reinterpret_cast<__half2*>(&r.y));
        float2 f2 = __half22float2(*reinterpret_cast<__half2*>(&r.z));
        float2 f3 = __half22float2(*reinterpret_cast<__half2*>(&r.w));
        a0.x = fmaf(w, f0.x, a0.x); a0.y = fmaf(w, f0.y, a0.y);
        a1.x = fmaf(w, f1.x, a1.x); a1.y = fmaf(w, f1.y, a1.y);
        a2.x = fmaf(w, f2.x, a2.x); a2.y = fmaf(w, f2.y, a2.y);
        a3.x = fmaf(w, f3.x, a3.x); a3.y = fmaf(w, f3.y, a3.y);
    }

    const float2* B2 = reinterpret_cast<const float2*>(b1);
    float2 bb0 = B2[lane * 4 + 0], bb1 = B2[lane * 4 + 1];
    float2 bb2 = B2[lane * 4 + 2], bb3 = B2[lane * 4 + 3];
    a0.x = fmaxf(a0.x + bb0.x, 0.f); a0.y = fmaxf(a0.y + bb0.y, 0.f);
    a1.x = fmaxf(a1.x + bb1.x, 0.f); a1.y = fmaxf(a1.y + bb1.y, 0.f);
    a2.x = fmaxf(a2.x + bb2.x, 0.f); a2.y = fmaxf(a2.y + bb2.y, 0.f);
    a3.x = fmaxf(a3.x + bb3.x, 0.f); a3.y = fmaxf(a3.y + bb3.y, 0.f);

    uint4 o;
    *reinterpret_cast<__half2*>(&o.x) = __float22half2_rn(a0);
    *reinterpret_cast<__half2*>(&o.y) = __float22half2_rn(a1);
    *reinterpret_cast<__half2*>(&o.z) = __float22half2_rn(a2);
    *reinterpret_cast<__half2*>(&o.w) = __float22half2_rn(a3);
    g_h1h[(size_t)n * 32 + lane] = o;
}

// ---------------- layer 2: agg(fp16 h1) -> f32x2 GEMM -> log_softmax ------
__global__ void __launch_bounds__(256) k_layer2(const int* __restrict__ mask,
                                                const float* __restrict__ W2,
                                                const float* __restrict__ b2,
                                                float* __restrict__ out) {
    __shared__ unsigned long long sagg2[DIM * SAGG_STRIDE];  // 20 KB
    const int t  = threadIdx.x;
    const int r0 = blockIdx.x * R2;
    const __half* H = reinterpret_cast<const __half*>(g_h1h);

    // ---- stage A: aggregate h1 rows; thread t owns feature dim t ----
    float a[R2];
    for (int i = 0; i < R2; i++) {
        const int m  = mask[r0 + i];
        const float dm = g_dinv[m];
        float acc = dm * dm * __half2float(H[(size_t)m * DIM + t]);
        const int e0 = g_rowstart[m];
        const int e1 = g_rowstart[m + 1];
        for (int e = e0; e < e1; e++) {
            int2 pw = g_csr[e];
            int   s = pw.x & 0xFFFFF;
            float w = __int_as_float(pw.y);
            acc = fmaf(w, __half2float(H[(size_t)s * DIM + t]), acc);
        }
        a[i] = acc;
    }
#pragma unroll
    for (int j = 0; j < 8; j++)
        sagg2[t * SAGG_STRIDE + j] = pk2(a[2 * j], a[2 * j + 1]);
    __syncthreads();

    // ---- stage B: packed f32x2 GEMM ----
    unsigned long long o2[8];
    {
        const float bb = b2[t];
        unsigned long long bbp = pk2(bb, bb);
#pragma unroll
        for (int j = 0; j < 8; j++) o2[j] = bbp;
    }
#pragma unroll 4
    for (int k = 0; k < DIM; k++) {
        const float w = W2[k * DIM + t];
        const unsigned long long ww = pk2(w, w);
        const ulonglong2* A2 = reinterpret_cast<const ulonglong2*>(sagg2 + k * SAGG_STRIDE);
        ulonglong2 p0 = A2[0], p1 = A2[1], p2 = A2[2], p3 = A2[3];
        fma2p(o2[0], p0.x, ww); fma2p(o2[1], p0.y, ww);
        fma2p(o2[2], p1.x, ww); fma2p(o2[3], p1.y, ww);
        fma2p(o2[4], p2.x, ww); fma2p(o2[5], p2.y, ww);
        fma2p(o2[6], p3.x, ww); fma2p(o2[7], p3.y, ww);
    }
    __syncthreads();

    float* sout = reinterpret_cast<float*>(sagg2);   // 16 KB <= 20 KB
#pragma unroll
    for (int j = 0; j < 8; j++) {
        float2 f = upk2(o2[j]);
        sout[(2 * j) * DIM + t]     = f.x;
        sout[(2 * j + 1) * DIM + t] = f.y;
    }
    __syncthreads();

    // ---- stage C: per-row log_softmax ----
    const int wi   = t >> 5;
    const int lane = t & 31;
#pragma unroll
    for (int rr = 0; rr < 2; rr++) {
        const int i = wi + rr * 8;
        float v[8];
        float mx = -INFINITY;
#pragma unroll
        for (int j = 0; j < 8; j++) {
            v[j] = sout[i * DIM + lane + j * 32];
            mx = fmaxf(mx, v[j]);
        }
#pragma unroll
        for (int off = 16; off > 0; off >>= 1)
            mx = fmaxf(mx, __shfl_xor_sync(0xFFFFFFFFu, mx, off));
        float s = 0.f;
#pragma unroll
        for (int j = 0; j < 8; j++) s += expf(v[j] - mx);
#pragma unroll
        for (int off = 16; off > 0; off >>= 1)
            s += __shfl_xor_sync(0xFFFFFFFFu, s, off);
        const float lse = mx + logf(s);
        float* orow = out + (size_t)(r0 + i) * DIM;
#pragma unroll
        for (int j = 0; j < 8; j++) orow[lane + j * 32] = v[j] - lse;
    }
}

// ---------------- launch ----------------
extern "C" void kernel_launch(void* const* d_in, const int* in_sizes, int n_in,
                              void* d_out, int out_size) {
    const int*   x    = (const int*)d_in[0];
    const int*   esrc = (const int*)d_in[1];
    const int*   edst = ((const int*)d_in[1]) + N_EDGES;
    const int*   mask = (const int*)d_in[2];
    const float* emb  = (const float*)d_in[3];
    const float* W1   = (const float*)d_in[4];
    const float* b1   = (const float*)d_in[5];
    const float* W2   = (const float*)d_in[6];
    const float* b2   = (const float*)d_in[7];
    float*       out  = (float*)d_out;

    void* p_z = nullptr;
    cudaGetSymbolAddress(&p_z, g_z);
    cudaMemsetAsync(p_z, 0, sizeof(ZeroRegion), 0);

    const int TB = 256;
    k_hist<<<(N_EDGES + TB - 1) / TB, TB>>>(edst);
    k_blocksum<<<NBLK, SCAN_B>>>();
    k_scanblocks<<<1, 128>>>();
    k_scanfinal<<<NBLK, SCAN_B>>>();
    k_fill<<<(N_EDGES + TB - 1) / TB, TB>>>(esrc, edst, x);
    k_mark<<<(N_MASK + 7) / 8, 256>>>(mask);
    k_ew1<<<VOCAB, DIM>>>(emb, W1);
    k_layer1<<<(N_NODES + 7) / 8, 256>>>(x, b1);
    k_layer2<<<N_MASK / R2, 256>>>(mask, W2, b2, out);
}